// round 13
// baseline (speedup 1.0000x reference)
#include <cuda_runtime.h>

#define BATCH 2
#define NBOX  1000
#define NCLS  80
#define NCAND 100
#define CAND  2048          // hard smem cap for filtered candidates per batch
#define BCAP  1024          // per-class staging stride (slot = box index)
#define NB    128           // histogram buckets (score bits >>19, rebased)
#define HBASE 1952          // (0x3D000000 >> 19): bucket of p = 1/32
#define TARGET 512          // candidate prefix size (>=100 survivors w/ margin)
#define PC 0.03125f         // stage only p >= 1/32 (bucket-aligned)

typedef unsigned long long u64;
typedef unsigned int u32;

// globals zero-initialized at load; every invocation self-cleans.
__device__ u64    g_bstage[BATCH * NCLS * BCAP];   // fixed-slot staged keys (0 = empty)
__device__ u32    g_hist [BATCH * NB];             // candidate score histogram
__device__ u32    g_hist2[BATCH * NB];             // survivor score histogram
__device__ int    g_scnt2[BATCH];                  // survivor counts
__device__ u64    g_surv[BATCH * CAND];            // survivor keys
__device__ float4 g_cbox[BATCH * NCLS * BCAP];     // survivor boxes by (c, rank)

__device__ __forceinline__ int bkt(u32 sb) {
    int v = (int)(sb >> 19) - HBASE;
    v = v < 0 ? 0 : v;
    return v > NB - 1 ? NB - 1 : v;
}

// ---------------------------------------------------------------------------
// K1: single-pass softmax; fixed-slot staging (no position atomics);
// histogram score bits. One warp per (b, n). 250 blocks x 256.
// ---------------------------------------------------------------------------
__global__ __launch_bounds__(256) void score_kernel(const float* __restrict__ cls) {
    int gw   = (blockIdx.x * blockDim.x + threadIdx.x) >> 5;
    int lane = threadIdx.x & 31;
    if (gw >= BATCH * NBOX) return;
    int b = gw / NBOX, n = gw % NBOX;

    const float* lg = cls + (size_t)(b * NBOX + n) * 81;

    float v0 = lg[lane];
    float v1 = lg[lane + 32];
    bool  ok2 = (lane + 64) < 81;
    float v2 = ok2 ? lg[lane + 64] : -1e30f;

    float mx = fmaxf(fmaxf(v0, v1), v2);
    #pragma unroll
    for (int o = 16; o; o >>= 1) mx = fmaxf(mx, __shfl_xor_sync(0xffffffffu, mx, o));

    float e0 = expf(v0 - mx);
    float e1 = expf(v1 - mx);
    float e2 = ok2 ? expf(v2 - mx) : 0.f;

    float s = e0 + e1 + e2;
    #pragma unroll
    for (int o = 16; o; o >>= 1) s += __shfl_xor_sync(0xffffffffu, s, o);
    float inv = 1.f / s;

    float pr[3] = { e0 * inv, e1 * inv, e2 * inv };

    #pragma unroll
    for (int h = 0; h < 3; h++) {
        int idx = lane + 32 * h;                 // logit index 0..80
        float p = pr[h];
        bool cls_ok = (idx >= 1) && (idx <= 80);
        u64 key = 0ull;
        if (cls_ok && p >= PC) {
            u32 sb = __float_as_uint(p);
            key = ((u64)sb << 10) | (u32)(1023 - n);
            atomicAdd(&g_hist[b * NB + bkt(sb)], 1u);
        }
        if (cls_ok) {
            int ci = b * NCLS + (idx - 1);
            g_bstage[(size_t)ci * BCAP + n] = key;   // key or 0, every run
        }
    }
}

// ---------------------------------------------------------------------------
// warp 0 helper: suffix-scan a 128-bucket histogram (4 buckets/lane).
//   mode 0: max(max v: suf>=TARGET, min v: suf<=CAND)  (candidates)
//   mode 1: max v: suf >= NCAND                        (survivors)
// ---------------------------------------------------------------------------
__device__ __forceinline__ int warp_threshold(const u32* hist, int mode) {
    int lane = threadIdx.x & 31;
    u32 h[4]; u32 L = 0;
    #pragma unroll
    for (int q = 0; q < 4; q++) { h[q] = hist[lane * 4 + q]; L += h[q]; }

    u32 x = L;                                    // inclusive suffix over lanes
    #pragma unroll
    for (int off = 1; off < 32; off <<= 1) {
        u32 t = __shfl_down_sync(0xffffffffu, x, off);
        if (lane + off < 32) x += t;
    }
    u32 run = x - L;                              // suffix strictly after chunk
    int t1 = 0, t2 = NB - 1;
    #pragma unroll
    for (int q = 3; q >= 0; q--) {
        u32 suf = run + h[q];
        int v = lane * 4 + q;
        if (mode == 0) {
            if (suf >= TARGET && v > t1) t1 = v;
            if (suf <= CAND   && v < t2) t2 = v;
        } else {
            if (suf >= NCAND  && v > t1) t1 = v;
        }
        run = suf;
    }
    #pragma unroll
    for (int off = 16; off; off >>= 1) {
        int a  = __shfl_xor_sync(0xffffffffu, t1, off);
        int bb = __shfl_xor_sync(0xffffffffu, t2, off);
        t1 = a  > t1 ? a  : t1;
        t2 = bb < t2 ? bb : t2;
    }
    return (mode == 0) ? (t1 > t2 ? t1 : t2) : t1;
}

// ---------------------------------------------------------------------------
// K2: per (b, class) — in-block threshold, filter, sort, decode, NMS,
// emit survivors. grid = BATCH*NCLS, block = 128.
// ---------------------------------------------------------------------------
__global__ __launch_bounds__(128) void class_nms_kernel(
        const float* __restrict__ box,
        const float* __restrict__ anc,
        const float* __restrict__ info) {
    __shared__ u64 skey[BCAP];
    __shared__ float4 sbx[BCAP];
    __shared__ unsigned char sflag[BCAP];
    __shared__ int s_n, s_cnt, s_base, s_tb;

    int tid = threadIdx.x;
    int ci  = blockIdx.x;
    int b   = ci / NCLS;
    int c   = ci % NCLS;

    if (tid == 0) s_n = 0;
    // warp 0: candidate threshold bucket (redundant per block; deterministic)
    if (tid < 32) {
        int tb = warp_threshold(g_hist + b * NB, 0);
        if (tid == 0) s_tb = tb;
    }
    __syncthreads();

    // filter fixed-slot staged keys by threshold bucket (coalesced scan)
    int tb = s_tb;
    for (int i = tid; i < NBOX; i += 128) {
        u64 k = g_bstage[(size_t)ci * BCAP + i];
        if (k != 0ull && bkt((u32)(k >> 10)) >= tb) {
            int p = atomicAdd(&s_n, 1);
            skey[p] = k;
        }
    }
    __syncthreads();
    int n = s_n;
    if (n == 0) return;

    // pad to pow2, bitonic sort descending (score, ~boxidx)
    int P = 32; while (P < n) P <<= 1;
    for (int e = tid; e < P; e += 128) if (e >= n) skey[e] = 0ull;
    for (unsigned k = 2; k <= (unsigned)P; k <<= 1) {
        for (unsigned j = k >> 1; j > 0; j >>= 1) {
            __syncthreads();
            for (int e = tid; e < P; e += 128) {
                int ixj = e ^ (int)j;
                if (ixj > e) {
                    u64 va = skey[e], vb = skey[ixj];
                    bool desc = ((e & (int)k) == 0);
                    if (desc ? (va < vb) : (va > vb)) { skey[e] = vb; skey[ixj] = va; }
                }
            }
        }
    }
    __syncthreads();

    // decode boxes (rank order)
    float hmax = info[b * 5 + 0] - 1.f;
    float wmax = info[b * 5 + 1] - 1.f;
    for (int i = tid; i < n; i += 128) {
        u64 k = skey[i];
        int nb = 1023 - (int)(k & 0x3FFull);
        float4 a = *(const float4*)(anc + (size_t)(b * NBOX + nb) * 4);
        float ha  = a.z - a.x + 1.f;
        float wa  = a.w - a.y + 1.f;
        float cya = a.x + 0.5f * ha;
        float cxa = a.y + 0.5f * wa;
        float4 e = *(const float4*)(box + ((size_t)(b * NBOX + nb) * 81 + (c + 1)) * 4);
        float cy = (e.x / 10.f) * ha + cya;
        float cx = (e.y / 10.f) * wa + cxa;
        float h  = expf(e.z / 5.f) * ha;
        float wd = expf(e.w / 5.f) * wa;
        float ymin = fminf(fmaxf(cy - 0.5f * h,        0.f), hmax);
        float ymax = fminf(fmaxf(cy + 0.5f * h - 1.f,  0.f), hmax);
        float xmin = fminf(fmaxf(cx - 0.5f * wd,       0.f), wmax);
        float xmax = fminf(fmaxf(cx + 0.5f * wd - 1.f, 0.f), wmax);
        sbx[i]   = make_float4(ymin, xmin, ymax, xmax);
        sflag[i] = 0;
    }
    __syncthreads();

    // greedy NMS: warp 0, serial over i, j-parallel over lanes
    if (tid < 32) {
        for (int i = 0; i < n - 1; i++) {
            if (sflag[i] == 0) {
                float4 B = sbx[i];
                float ai = (B.z - B.x) * (B.w - B.y);
                for (int j = i + 1 + tid; j < n; j += 32) {
                    float4 C = sbx[j];
                    float iy = fmaxf(0.f, fminf(B.z, C.z) - fmaxf(B.x, C.x));
                    float ix = fmaxf(0.f, fminf(B.w, C.w) - fmaxf(B.y, C.y));
                    float inter = iy * ix;
                    float aj  = (C.z - C.x) * (C.w - C.y);
                    float iou = inter / fmaxf(ai + aj - inter, 1e-8f);  // exact ref
                    if (iou > 0.5f) sflag[j] = 1;
                }
            }
            __syncwarp();
        }
    }
    __syncthreads();

    // reserve global survivor slots
    if (tid == 0) s_cnt = 0;
    __syncthreads();
    int my = 0;
    for (int e = tid; e < n; e += 128) if (!sflag[e]) my++;
    if (my) atomicAdd(&s_cnt, my);
    __syncthreads();
    if (tid == 0) s_base = atomicAdd(&g_scnt2[b], s_cnt);
    __syncthreads();
    if (tid == 0) s_cnt = 0;
    __syncthreads();

    // emit survivors: key (score desc, (c,rank) asc proxy), box, histogram
    for (int e = tid; e < n; e += 128) {
        if (!sflag[e]) {
            u32 sb   = (u32)(skey[e] >> 10);
            u32 flat = (u32)(c * BCAP + e);            // rank == true class rank
            int slot = atomicAdd(&s_cnt, 1);
            g_surv[b * CAND + s_base + slot] =
                ((u64)sb << 18) | (u64)(0x3FFFFu ^ flat);
            g_cbox[(size_t)ci * BCAP + e] = sbx[e];
            atomicAdd(&g_hist2[b * NB + bkt(sb)], 1u);
        }
    }
}

// ---------------------------------------------------------------------------
// K3: per batch — survivor threshold for top-100, small sort, emit output,
// all cleanup. grid = BATCH, block = 128.
// ---------------------------------------------------------------------------
__global__ __launch_bounds__(128) void final_kernel(float* __restrict__ out) {
    __shared__ u64 skey[CAND];
    __shared__ int s_tb, s_n;

    int tid = threadIdx.x;
    int b   = blockIdx.x;

    if (tid == 0) s_n = 0;
    if (tid < 32) {
        int tb = warp_threshold(g_hist2 + b * NB, 1);
        if (tid == 0) s_tb = tb;
    }
    __syncthreads();

    int tb2 = s_tb;

    // filter survivors above the bucket threshold
    int tot = g_scnt2[b];
    for (int i = tid; i < tot; i += 128) {
        u64 k = g_surv[b * CAND + i];
        if (bkt((u32)(k >> 18)) >= tb2) {
            int p = atomicAdd(&s_n, 1);
            skey[p] = k;                      // <= CAND by construction
        }
    }
    __syncthreads();
    int n = s_n;                              // typ. ~100-200

    int P = 128; while (P < n) P <<= 1;       // <= CAND
    for (int e = tid; e < P; e += 128) if (e >= n) skey[e] = 0ull;
    for (unsigned k = 2; k <= (unsigned)P; k <<= 1) {
        for (unsigned j = k >> 1; j > 0; j >>= 1) {
            __syncthreads();
            for (int e = tid; e < P; e += 128) {
                int ixj = e ^ (int)j;
                if (ixj > e) {
                    u64 va = skey[e], vb = skey[ixj];
                    bool desc = ((e & (int)k) == 0);
                    if (desc ? (va < vb) : (va > vb)) { skey[e] = vb; skey[ixj] = va; }
                }
            }
        }
    }
    __syncthreads();

    // emit top-100
    if (tid < NCAND) {
        u64 kv   = skey[tid];
        u32 sb   = (u32)(kv >> 18);
        u32 flat = 0x3FFFFu ^ ((u32)kv & 0x3FFFFu);
        int c    = (int)(flat >> 10);
        int rank = (int)(flat & (BCAP - 1));
        float4 bx = g_cbox[(size_t)(b * NCLS + c) * BCAP + rank];
        float* o = out + (size_t)(b * NCAND + tid) * 6;
        o[0] = bx.x; o[1] = bx.y; o[2] = bx.z; o[3] = bx.w;
        o[4] = __uint_as_float(sb);
        o[5] = (float)(c + 1);
    }

    // cleanup for next invocation
    if (tid < NB) {
        g_hist [b * NB + tid] = 0;
        g_hist2[b * NB + tid] = 0;
    }
    if (tid == 0) g_scnt2[b] = 0;
}

// ---------------------------------------------------------------------------
extern "C" void kernel_launch(void* const* d_in, const int* in_sizes, int n_in,
                              void* d_out, int out_size) {
    const float* cls  = (const float*)d_in[0];
    const float* box  = (const float*)d_in[1];
    const float* anc  = (const float*)d_in[2];
    const float* info = (const float*)d_in[3];

    score_kernel<<<(BATCH * NBOX * 32 + 255) / 256, 256>>>(cls);
    class_nms_kernel<<<BATCH * NCLS, 128>>>(box, anc, info);
    final_kernel<<<BATCH, 128>>>((float*)d_out);
}

// round 14
// speedup vs baseline: 1.1795x; 1.1795x over previous
#include <cuda_runtime.h>

#define BATCH 2
#define NBOX  1000
#define NCLS  80
#define NCAND 100
#define CAND  2048          // hard smem cap for filtered candidates per batch
#define BCAP  1024          // per-class staging capacity (<=1000 used)
#define NB    128           // histogram buckets (score bits >>19, rebased)
#define HBASE 1952          // (0x3D000000 >> 19): bucket of p = 1/32
#define TARGET 256          // candidate prefix size (>=100 survivors w/ margin)
#define PC 0.03125f         // stage only p >= 1/32 (bucket-aligned)

typedef unsigned long long u64;
typedef unsigned int u32;

// globals zero-initialized at load; every invocation self-cleans.
__device__ int    g_bcnt[BATCH * NCLS];            // per-class staged counts
__device__ u64    g_bstage[BATCH * NCLS * BCAP];   // per-class staged keys
__device__ u32    g_hist [BATCH * NB];             // candidate score histogram
__device__ u32    g_hist2[BATCH * NB];             // survivor score histogram
__device__ int    g_scnt2[BATCH];                  // survivor counts
__device__ u64    g_surv[BATCH * CAND];            // survivor keys
__device__ float4 g_cbox[BATCH * NCLS * BCAP];     // survivor boxes by (c, rank)

__device__ __forceinline__ int bkt(u32 sb) {
    int v = (int)(sb >> 19) - HBASE;
    v = v < 0 ? 0 : v;
    return v > NB - 1 ? NB - 1 : v;
}

// ---------------------------------------------------------------------------
// K1: single-pass softmax; stage (score, ~boxidx) into per-class buckets;
// histogram score bits. One warp per (b, n). 250 blocks x 256.
// ---------------------------------------------------------------------------
__global__ __launch_bounds__(256) void score_kernel(const float* __restrict__ cls) {
    int gw   = (blockIdx.x * blockDim.x + threadIdx.x) >> 5;
    int lane = threadIdx.x & 31;
    if (gw >= BATCH * NBOX) return;
    int b = gw / NBOX, n = gw % NBOX;

    const float* lg = cls + (size_t)(b * NBOX + n) * 81;

    float v0 = lg[lane];
    float v1 = lg[lane + 32];
    bool  ok2 = (lane + 64) < 81;
    float v2 = ok2 ? lg[lane + 64] : -1e30f;

    float mx = fmaxf(fmaxf(v0, v1), v2);
    #pragma unroll
    for (int o = 16; o; o >>= 1) mx = fmaxf(mx, __shfl_xor_sync(0xffffffffu, mx, o));

    float e0 = expf(v0 - mx);
    float e1 = expf(v1 - mx);
    float e2 = ok2 ? expf(v2 - mx) : 0.f;

    float s = e0 + e1 + e2;
    #pragma unroll
    for (int o = 16; o; o >>= 1) s += __shfl_xor_sync(0xffffffffu, s, o);
    float inv = 1.f / s;

    float pr[3] = { e0 * inv, e1 * inv, e2 * inv };

    #pragma unroll
    for (int h = 0; h < 3; h++) {
        int idx = lane + 32 * h;                 // logit index 0..80
        float p = pr[h];
        if (idx >= 1 && idx <= 80 && p >= PC) {
            u32 sb = __float_as_uint(p);
            int ci = b * NCLS + (idx - 1);
            int pos = atomicAdd(&g_bcnt[ci], 1);  // < 1000 always
            g_bstage[(size_t)ci * BCAP + pos] = ((u64)sb << 10) | (u32)(1023 - n);
            atomicAdd(&g_hist[b * NB + bkt(sb)], 1u);
        }
    }
}

// ---------------------------------------------------------------------------
// warp 0 helper: suffix-scan a 128-bucket histogram (4 buckets/lane).
//   mode 0: max(max v: suf>=TARGET, min v: suf<=CAND)  (candidates)
//   mode 1: max v: suf >= NCAND                        (survivors)
// ---------------------------------------------------------------------------
__device__ __forceinline__ int warp_threshold(const u32* hist, int mode) {
    int lane = threadIdx.x & 31;
    u32 h[4]; u32 L = 0;
    #pragma unroll
    for (int q = 0; q < 4; q++) { h[q] = hist[lane * 4 + q]; L += h[q]; }

    u32 x = L;                                    // inclusive suffix over lanes
    #pragma unroll
    for (int off = 1; off < 32; off <<= 1) {
        u32 t = __shfl_down_sync(0xffffffffu, x, off);
        if (lane + off < 32) x += t;
    }
    u32 run = x - L;                              // suffix strictly after chunk
    int t1 = 0, t2 = NB - 1;
    #pragma unroll
    for (int q = 3; q >= 0; q--) {
        u32 suf = run + h[q];
        int v = lane * 4 + q;
        if (mode == 0) {
            if (suf >= TARGET && v > t1) t1 = v;
            if (suf <= CAND   && v < t2) t2 = v;
        } else {
            if (suf >= NCAND  && v > t1) t1 = v;
        }
        run = suf;
    }
    #pragma unroll
    for (int off = 16; off; off >>= 1) {
        int a  = __shfl_xor_sync(0xffffffffu, t1, off);
        int bb = __shfl_xor_sync(0xffffffffu, t2, off);
        t1 = a  > t1 ? a  : t1;
        t2 = bb < t2 ? bb : t2;
    }
    return (mode == 0) ? (t1 > t2 ? t1 : t2) : t1;
}

// ---------------------------------------------------------------------------
// K2: per (b, class) — in-block threshold, filter, sort, decode, NMS,
// emit survivors. grid = BATCH*NCLS, block = 128.
// ---------------------------------------------------------------------------
__global__ __launch_bounds__(128) void class_nms_kernel(
        const float* __restrict__ box,
        const float* __restrict__ anc,
        const float* __restrict__ info) {
    __shared__ u64 skey[BCAP];
    __shared__ float4 sbx[BCAP];
    __shared__ unsigned char sflag[BCAP];
    __shared__ int s_n, s_cnt, s_base, s_tb;

    int tid = threadIdx.x;
    int ci  = blockIdx.x;
    int b   = ci / NCLS;
    int c   = ci % NCLS;

    if (tid == 0) s_n = 0;
    // warp 0: candidate threshold bucket (redundant per block; deterministic)
    if (tid < 32) {
        int tb = warp_threshold(g_hist + b * NB, 0);
        if (tid == 0) s_tb = tb;
    }
    __syncthreads();

    // filter staged keys by threshold bucket
    int m  = g_bcnt[ci];
    int tb = s_tb;
    for (int i = tid; i < m; i += 128) {
        u64 k = g_bstage[(size_t)ci * BCAP + i];
        if (bkt((u32)(k >> 10)) >= tb) {
            int p = atomicAdd(&s_n, 1);
            skey[p] = k;
        }
    }
    __syncthreads();
    int n = s_n;
    if (tid == 0) g_bcnt[ci] = 0;          // cleanup for next invocation
    if (n == 0) return;

    // pad to pow2, bitonic sort descending (score, ~boxidx)
    int P = 32; while (P < n) P <<= 1;
    for (int e = tid; e < P; e += 128) if (e >= n) skey[e] = 0ull;
    for (unsigned k = 2; k <= (unsigned)P; k <<= 1) {
        for (unsigned j = k >> 1; j > 0; j >>= 1) {
            __syncthreads();
            for (int e = tid; e < P; e += 128) {
                int ixj = e ^ (int)j;
                if (ixj > e) {
                    u64 va = skey[e], vb = skey[ixj];
                    bool desc = ((e & (int)k) == 0);
                    if (desc ? (va < vb) : (va > vb)) { skey[e] = vb; skey[ixj] = va; }
                }
            }
        }
    }
    __syncthreads();

    // decode boxes (rank order)
    float hmax = info[b * 5 + 0] - 1.f;
    float wmax = info[b * 5 + 1] - 1.f;
    for (int i = tid; i < n; i += 128) {
        u64 k = skey[i];
        int nb = 1023 - (int)(k & 0x3FFull);
        float4 a = *(const float4*)(anc + (size_t)(b * NBOX + nb) * 4);
        float ha  = a.z - a.x + 1.f;
        float wa  = a.w - a.y + 1.f;
        float cya = a.x + 0.5f * ha;
        float cxa = a.y + 0.5f * wa;
        float4 e = *(const float4*)(box + ((size_t)(b * NBOX + nb) * 81 + (c + 1)) * 4);
        float cy = (e.x / 10.f) * ha + cya;
        float cx = (e.y / 10.f) * wa + cxa;
        float h  = expf(e.z / 5.f) * ha;
        float wd = expf(e.w / 5.f) * wa;
        float ymin = fminf(fmaxf(cy - 0.5f * h,        0.f), hmax);
        float ymax = fminf(fmaxf(cy + 0.5f * h - 1.f,  0.f), hmax);
        float xmin = fminf(fmaxf(cx - 0.5f * wd,       0.f), wmax);
        float xmax = fminf(fmaxf(cx + 0.5f * wd - 1.f, 0.f), wmax);
        sbx[i]   = make_float4(ymin, xmin, ymax, xmax);
        sflag[i] = 0;
    }
    __syncthreads();

    // greedy NMS: warp 0, serial over i, j-parallel over lanes
    if (tid < 32) {
        for (int i = 0; i < n - 1; i++) {
            if (sflag[i] == 0) {
                float4 B = sbx[i];
                float ai = (B.z - B.x) * (B.w - B.y);
                for (int j = i + 1 + tid; j < n; j += 32) {
                    float4 C = sbx[j];
                    float iy = fmaxf(0.f, fminf(B.z, C.z) - fmaxf(B.x, C.x));
                    float ix = fmaxf(0.f, fminf(B.w, C.w) - fmaxf(B.y, C.y));
                    float inter = iy * ix;
                    float aj  = (C.z - C.x) * (C.w - C.y);
                    float iou = inter / fmaxf(ai + aj - inter, 1e-8f);  // exact ref
                    if (iou > 0.5f) sflag[j] = 1;
                }
            }
            __syncwarp();
        }
    }
    __syncthreads();

    // reserve global survivor slots
    if (tid == 0) s_cnt = 0;
    __syncthreads();
    int my = 0;
    for (int e = tid; e < n; e += 128) if (!sflag[e]) my++;
    if (my) atomicAdd(&s_cnt, my);
    __syncthreads();
    if (tid == 0) s_base = atomicAdd(&g_scnt2[b], s_cnt);
    __syncthreads();
    if (tid == 0) s_cnt = 0;
    __syncthreads();

    // emit survivors: key (score desc, (c,rank) asc proxy), box, histogram
    for (int e = tid; e < n; e += 128) {
        if (!sflag[e]) {
            u32 sb   = (u32)(skey[e] >> 10);
            u32 flat = (u32)(c * BCAP + e);            // rank == true class rank
            int slot = atomicAdd(&s_cnt, 1);
            g_surv[b * CAND + s_base + slot] =
                ((u64)sb << 18) | (u64)(0x3FFFFu ^ flat);
            g_cbox[(size_t)ci * BCAP + e] = sbx[e];
            atomicAdd(&g_hist2[b * NB + bkt(sb)], 1u);
        }
    }
}

// ---------------------------------------------------------------------------
// K3: per batch — survivor threshold for top-100, small sort, emit output,
// all cleanup. grid = BATCH, block = 128.
// ---------------------------------------------------------------------------
__global__ __launch_bounds__(128) void final_kernel(float* __restrict__ out) {
    __shared__ u64 skey[CAND];
    __shared__ int s_tb, s_n;

    int tid = threadIdx.x;
    int b   = blockIdx.x;

    if (tid == 0) s_n = 0;
    if (tid < 32) {
        int tb = warp_threshold(g_hist2 + b * NB, 1);
        if (tid == 0) s_tb = tb;
    }
    __syncthreads();

    int tb2 = s_tb;

    // filter survivors above the bucket threshold
    int tot = g_scnt2[b];
    for (int i = tid; i < tot; i += 128) {
        u64 k = g_surv[b * CAND + i];
        if (bkt((u32)(k >> 18)) >= tb2) {
            int p = atomicAdd(&s_n, 1);
            skey[p] = k;                      // <= CAND by construction
        }
    }
    __syncthreads();
    int n = s_n;                              // typ. ~100-150

    int P = 128; while (P < n) P <<= 1;       // <= CAND
    for (int e = tid; e < P; e += 128) if (e >= n) skey[e] = 0ull;
    for (unsigned k = 2; k <= (unsigned)P; k <<= 1) {
        for (unsigned j = k >> 1; j > 0; j >>= 1) {
            __syncthreads();
            for (int e = tid; e < P; e += 128) {
                int ixj = e ^ (int)j;
                if (ixj > e) {
                    u64 va = skey[e], vb = skey[ixj];
                    bool desc = ((e & (int)k) == 0);
                    if (desc ? (va < vb) : (va > vb)) { skey[e] = vb; skey[ixj] = va; }
                }
            }
        }
    }
    __syncthreads();

    // emit top-100
    if (tid < NCAND) {
        u64 kv   = skey[tid];
        u32 sb   = (u32)(kv >> 18);
        u32 flat = 0x3FFFFu ^ ((u32)kv & 0x3FFFFu);
        int c    = (int)(flat >> 10);
        int rank = (int)(flat & (BCAP - 1));
        float4 bx = g_cbox[(size_t)(b * NCLS + c) * BCAP + rank];
        float* o = out + (size_t)(b * NCAND + tid) * 6;
        o[0] = bx.x; o[1] = bx.y; o[2] = bx.z; o[3] = bx.w;
        o[4] = __uint_as_float(sb);
        o[5] = (float)(c + 1);
    }

    // cleanup for next invocation
    if (tid < NB) {
        g_hist [b * NB + tid] = 0;
        g_hist2[b * NB + tid] = 0;
    }
    if (tid == 0) g_scnt2[b] = 0;
}

// ---------------------------------------------------------------------------
extern "C" void kernel_launch(void* const* d_in, const int* in_sizes, int n_in,
                              void* d_out, int out_size) {
    const float* cls  = (const float*)d_in[0];
    const float* box  = (const float*)d_in[1];
    const float* anc  = (const float*)d_in[2];
    const float* info = (const float*)d_in[3];

    score_kernel<<<(BATCH * NBOX * 32 + 255) / 256, 256>>>(cls);
    class_nms_kernel<<<BATCH * NCLS, 128>>>(box, anc, info);
    final_kernel<<<BATCH, 128>>>((float*)d_out);
}

// round 15
// speedup vs baseline: 1.2217x; 1.0358x over previous
#include <cuda_runtime.h>

#define BATCH 2
#define NBOX  1000
#define NCLS  80
#define NCAND 100
#define CAND  2048          // hard smem cap for filtered candidates per batch
#define BCAP  1024          // per-class staging capacity (<=1000 used)
#define NB    128           // histogram buckets (score bits >>19, rebased)
#define HBASE 1952          // (0x3D000000 >> 19): bucket of p = 1/32
#define TARGET 256          // candidate prefix size (>=100 survivors w/ margin)
#define PC 0.03125f         // stage only p >= 1/32 (bucket-aligned)

typedef unsigned long long u64;
typedef unsigned int u32;

// globals zero-initialized at load; every invocation self-cleans.
__device__ int    g_bcnt[BATCH * NCLS];            // per-class staged counts
__device__ u64    g_bstage[BATCH * NCLS * BCAP];   // per-class staged keys
__device__ u32    g_hist [BATCH * NB];             // candidate score histogram
__device__ u32    g_hist2[BATCH * NB];             // survivor score histogram
__device__ int    g_scnt2[BATCH];                  // survivor counts
__device__ u64    g_surv[BATCH * CAND];            // survivor keys
__device__ float4 g_cbox[BATCH * NCLS * BCAP];     // survivor boxes by (c, rank)

__device__ __forceinline__ int bkt(u32 sb) {
    int v = (int)(sb >> 19) - HBASE;
    v = v < 0 ? 0 : v;
    return v > NB - 1 ? NB - 1 : v;
}

// ---------------------------------------------------------------------------
// K1: single-pass softmax; stage (score, ~boxidx) into per-class buckets;
// histogram score bits. One warp per (b, n). 250 blocks x 256.
// ---------------------------------------------------------------------------
__global__ __launch_bounds__(256) void score_kernel(const float* __restrict__ cls) {
    int gw   = (blockIdx.x * blockDim.x + threadIdx.x) >> 5;
    int lane = threadIdx.x & 31;
    if (gw >= BATCH * NBOX) { cudaTriggerProgrammaticLaunchCompletion(); return; }
    int b = gw / NBOX, n = gw % NBOX;

    const float* lg = cls + (size_t)(b * NBOX + n) * 81;

    float v0 = lg[lane];
    float v1 = lg[lane + 32];
    bool  ok2 = (lane + 64) < 81;
    float v2 = ok2 ? lg[lane + 64] : -1e30f;

    float mx = fmaxf(fmaxf(v0, v1), v2);
    #pragma unroll
    for (int o = 16; o; o >>= 1) mx = fmaxf(mx, __shfl_xor_sync(0xffffffffu, mx, o));

    float e0 = expf(v0 - mx);
    float e1 = expf(v1 - mx);
    float e2 = ok2 ? expf(v2 - mx) : 0.f;

    float s = e0 + e1 + e2;
    #pragma unroll
    for (int o = 16; o; o >>= 1) s += __shfl_xor_sync(0xffffffffu, s, o);
    float inv = 1.f / s;

    float pr[3] = { e0 * inv, e1 * inv, e2 * inv };

    #pragma unroll
    for (int h = 0; h < 3; h++) {
        int idx = lane + 32 * h;                 // logit index 0..80
        float p = pr[h];
        if (idx >= 1 && idx <= 80 && p >= PC) {
            u32 sb = __float_as_uint(p);
            int ci = b * NCLS + (idx - 1);
            int pos = atomicAdd(&g_bcnt[ci], 1);  // < 1000 always
            g_bstage[(size_t)ci * BCAP + pos] = ((u64)sb << 10) | (u32)(1023 - n);
            atomicAdd(&g_hist[b * NB + bkt(sb)], 1u);
        }
    }
    cudaTriggerProgrammaticLaunchCompletion();
}

// ---------------------------------------------------------------------------
// warp 0 helper: suffix-scan a 128-bucket histogram (4 buckets/lane).
//   mode 0: max(max v: suf>=TARGET, min v: suf<=CAND)  (candidates)
//   mode 1: max v: suf >= NCAND                        (survivors)
// ---------------------------------------------------------------------------
__device__ __forceinline__ int warp_threshold(const u32* hist, int mode) {
    int lane = threadIdx.x & 31;
    u32 h[4]; u32 L = 0;
    #pragma unroll
    for (int q = 0; q < 4; q++) { h[q] = hist[lane * 4 + q]; L += h[q]; }

    u32 x = L;                                    // inclusive suffix over lanes
    #pragma unroll
    for (int off = 1; off < 32; off <<= 1) {
        u32 t = __shfl_down_sync(0xffffffffu, x, off);
        if (lane + off < 32) x += t;
    }
    u32 run = x - L;                              // suffix strictly after chunk
    int t1 = 0, t2 = NB - 1;
    #pragma unroll
    for (int q = 3; q >= 0; q--) {
        u32 suf = run + h[q];
        int v = lane * 4 + q;
        if (mode == 0) {
            if (suf >= TARGET && v > t1) t1 = v;
            if (suf <= CAND   && v < t2) t2 = v;
        } else {
            if (suf >= NCAND  && v > t1) t1 = v;
        }
        run = suf;
    }
    #pragma unroll
    for (int off = 16; off; off >>= 1) {
        int a  = __shfl_xor_sync(0xffffffffu, t1, off);
        int bb = __shfl_xor_sync(0xffffffffu, t2, off);
        t1 = a  > t1 ? a  : t1;
        t2 = bb < t2 ? bb : t2;
    }
    return (mode == 0) ? (t1 > t2 ? t1 : t2) : t1;
}

// ---------------------------------------------------------------------------
// K2: per (b, class) — PDL wait, in-block threshold, filter, sort, decode,
// NMS, emit survivors. grid = BATCH*NCLS, block = 128.
// ---------------------------------------------------------------------------
__global__ __launch_bounds__(128) void class_nms_kernel(
        const float* __restrict__ box,
        const float* __restrict__ anc,
        const float* __restrict__ info) {
    __shared__ u64 skey[BCAP];
    __shared__ float4 sbx[BCAP];
    __shared__ unsigned char sflag[BCAP];
    __shared__ int s_n, s_cnt, s_base, s_tb;

    // wait until score_kernel is complete and its writes are visible
    cudaGridDependencySynchronize();

    int tid = threadIdx.x;
    int ci  = blockIdx.x;
    int b   = ci / NCLS;
    int c   = ci % NCLS;

    if (tid == 0) s_n = 0;
    // warp 0: candidate threshold bucket (redundant per block; deterministic)
    if (tid < 32) {
        int tb = warp_threshold(g_hist + b * NB, 0);
        if (tid == 0) s_tb = tb;
    }
    __syncthreads();

    // filter staged keys by threshold bucket
    int m  = g_bcnt[ci];
    int tb = s_tb;
    for (int i = tid; i < m; i += 128) {
        u64 k = g_bstage[(size_t)ci * BCAP + i];
        if (bkt((u32)(k >> 10)) >= tb) {
            int p = atomicAdd(&s_n, 1);
            skey[p] = k;
        }
    }
    __syncthreads();
    int n = s_n;
    if (tid == 0) g_bcnt[ci] = 0;          // cleanup for next invocation
    if (n == 0) { cudaTriggerProgrammaticLaunchCompletion(); return; }

    // pad to pow2, bitonic sort descending (score, ~boxidx)
    int P = 32; while (P < n) P <<= 1;
    for (int e = tid; e < P; e += 128) if (e >= n) skey[e] = 0ull;
    for (unsigned k = 2; k <= (unsigned)P; k <<= 1) {
        for (unsigned j = k >> 1; j > 0; j >>= 1) {
            __syncthreads();
            for (int e = tid; e < P; e += 128) {
                int ixj = e ^ (int)j;
                if (ixj > e) {
                    u64 va = skey[e], vb = skey[ixj];
                    bool desc = ((e & (int)k) == 0);
                    if (desc ? (va < vb) : (va > vb)) { skey[e] = vb; skey[ixj] = va; }
                }
            }
        }
    }
    __syncthreads();

    // decode boxes (rank order)
    float hmax = info[b * 5 + 0] - 1.f;
    float wmax = info[b * 5 + 1] - 1.f;
    for (int i = tid; i < n; i += 128) {
        u64 k = skey[i];
        int nb = 1023 - (int)(k & 0x3FFull);
        float4 a = *(const float4*)(anc + (size_t)(b * NBOX + nb) * 4);
        float ha  = a.z - a.x + 1.f;
        float wa  = a.w - a.y + 1.f;
        float cya = a.x + 0.5f * ha;
        float cxa = a.y + 0.5f * wa;
        float4 e = *(const float4*)(box + ((size_t)(b * NBOX + nb) * 81 + (c + 1)) * 4);
        float cy = (e.x / 10.f) * ha + cya;
        float cx = (e.y / 10.f) * wa + cxa;
        float h  = expf(e.z / 5.f) * ha;
        float wd = expf(e.w / 5.f) * wa;
        float ymin = fminf(fmaxf(cy - 0.5f * h,        0.f), hmax);
        float ymax = fminf(fmaxf(cy + 0.5f * h - 1.f,  0.f), hmax);
        float xmin = fminf(fmaxf(cx - 0.5f * wd,       0.f), wmax);
        float xmax = fminf(fmaxf(cx + 0.5f * wd - 1.f, 0.f), wmax);
        sbx[i]   = make_float4(ymin, xmin, ymax, xmax);
        sflag[i] = 0;
    }
    __syncthreads();

    // greedy NMS: warp 0, serial over i, j-parallel over lanes
    if (tid < 32) {
        for (int i = 0; i < n - 1; i++) {
            if (sflag[i] == 0) {
                float4 B = sbx[i];
                float ai = (B.z - B.x) * (B.w - B.y);
                for (int j = i + 1 + tid; j < n; j += 32) {
                    float4 C = sbx[j];
                    float iy = fmaxf(0.f, fminf(B.z, C.z) - fmaxf(B.x, C.x));
                    float ix = fmaxf(0.f, fminf(B.w, C.w) - fmaxf(B.y, C.y));
                    float inter = iy * ix;
                    float aj  = (C.z - C.x) * (C.w - C.y);
                    float iou = inter / fmaxf(ai + aj - inter, 1e-8f);  // exact ref
                    if (iou > 0.5f) sflag[j] = 1;
                }
            }
            __syncwarp();
        }
    }
    __syncthreads();

    // reserve global survivor slots
    if (tid == 0) s_cnt = 0;
    __syncthreads();
    int my = 0;
    for (int e = tid; e < n; e += 128) if (!sflag[e]) my++;
    if (my) atomicAdd(&s_cnt, my);
    __syncthreads();
    if (tid == 0) s_base = atomicAdd(&g_scnt2[b], s_cnt);
    __syncthreads();
    if (tid == 0) s_cnt = 0;
    __syncthreads();

    // emit survivors: key (score desc, (c,rank) asc proxy), box, histogram
    for (int e = tid; e < n; e += 128) {
        if (!sflag[e]) {
            u32 sb   = (u32)(skey[e] >> 10);
            u32 flat = (u32)(c * BCAP + e);            // rank == true class rank
            int slot = atomicAdd(&s_cnt, 1);
            g_surv[b * CAND + s_base + slot] =
                ((u64)sb << 18) | (u64)(0x3FFFFu ^ flat);
            g_cbox[(size_t)ci * BCAP + e] = sbx[e];
            atomicAdd(&g_hist2[b * NB + bkt(sb)], 1u);
        }
    }
    cudaTriggerProgrammaticLaunchCompletion();
}

// ---------------------------------------------------------------------------
// K3: per batch — PDL wait, survivor threshold for top-100, small sort,
// emit output, all cleanup. grid = BATCH, block = 128.
// ---------------------------------------------------------------------------
__global__ __launch_bounds__(128) void final_kernel(float* __restrict__ out) {
    __shared__ u64 skey[CAND];
    __shared__ int s_tb, s_n;

    // wait until class_nms_kernel is complete and its writes are visible
    cudaGridDependencySynchronize();

    int tid = threadIdx.x;
    int b   = blockIdx.x;

    if (tid == 0) s_n = 0;
    if (tid < 32) {
        int tb = warp_threshold(g_hist2 + b * NB, 1);
        if (tid == 0) s_tb = tb;
    }
    __syncthreads();

    int tb2 = s_tb;

    // filter survivors above the bucket threshold
    int tot = g_scnt2[b];
    for (int i = tid; i < tot; i += 128) {
        u64 k = g_surv[b * CAND + i];
        if (bkt((u32)(k >> 18)) >= tb2) {
            int p = atomicAdd(&s_n, 1);
            skey[p] = k;                      // <= CAND by construction
        }
    }
    __syncthreads();
    int n = s_n;                              // typ. ~100-150

    int P = 128; while (P < n) P <<= 1;       // <= CAND
    for (int e = tid; e < P; e += 128) if (e >= n) skey[e] = 0ull;
    for (unsigned k = 2; k <= (unsigned)P; k <<= 1) {
        for (unsigned j = k >> 1; j > 0; j >>= 1) {
            __syncthreads();
            for (int e = tid; e < P; e += 128) {
                int ixj = e ^ (int)j;
                if (ixj > e) {
                    u64 va = skey[e], vb = skey[ixj];
                    bool desc = ((e & (int)k) == 0);
                    if (desc ? (va < vb) : (va > vb)) { skey[e] = vb; skey[ixj] = va; }
                }
            }
        }
    }
    __syncthreads();

    // emit top-100
    if (tid < NCAND) {
        u64 kv   = skey[tid];
        u32 sb   = (u32)(kv >> 18);
        u32 flat = 0x3FFFFu ^ ((u32)kv & 0x3FFFFu);
        int c    = (int)(flat >> 10);
        int rank = (int)(flat & (BCAP - 1));
        float4 bx = g_cbox[(size_t)(b * NCLS + c) * BCAP + rank];
        float* o = out + (size_t)(b * NCAND + tid) * 6;
        o[0] = bx.x; o[1] = bx.y; o[2] = bx.z; o[3] = bx.w;
        o[4] = __uint_as_float(sb);
        o[5] = (float)(c + 1);
    }

    // cleanup for next invocation
    if (tid < NB) {
        g_hist [b * NB + tid] = 0;
        g_hist2[b * NB + tid] = 0;
    }
    if (tid == 0) g_scnt2[b] = 0;
}

// ---------------------------------------------------------------------------
extern "C" void kernel_launch(void* const* d_in, const int* in_sizes, int n_in,
                              void* d_out, int out_size) {
    const float* cls  = (const float*)d_in[0];
    const float* box  = (const float*)d_in[1];
    const float* anc  = (const float*)d_in[2];
    const float* info = (const float*)d_in[3];

    // K1: plain launch on the capture stream
    score_kernel<<<(BATCH * NBOX * 32 + 255) / 256, 256>>>(cls);

    // K2, K3: programmatic dependent launches (overlap launch with upstream tail)
    cudaLaunchAttribute attr[1];
    attr[0].id = cudaLaunchAttributeProgrammaticStreamSerialization;
    attr[0].val.programmaticStreamSerializationAllowed = 1;

    {
        cudaLaunchConfig_t cfg = {};
        cfg.gridDim  = dim3(BATCH * NCLS, 1, 1);
        cfg.blockDim = dim3(128, 1, 1);
        cfg.dynamicSmemBytes = 0;
        cfg.stream = 0;
        cfg.attrs = attr;
        cfg.numAttrs = 1;
        cudaLaunchKernelEx(&cfg, class_nms_kernel, box, anc, info);
    }
    {
        cudaLaunchConfig_t cfg = {};
        cfg.gridDim  = dim3(BATCH, 1, 1);
        cfg.blockDim = dim3(128, 1, 1);
        cfg.dynamicSmemBytes = 0;
        cfg.stream = 0;
        cfg.attrs = attr;
        cfg.numAttrs = 1;
        cudaLaunchKernelEx(&cfg, final_kernel, (float*)d_out);
    }
}

// round 16
// speedup vs baseline: 1.2610x; 1.0322x over previous
#include <cuda_runtime.h>

#define BATCH 2
#define NBOX  1000
#define NCLS  80
#define NCAND 100
#define CAND  2048          // hard smem cap for filtered candidates per batch
#define BCAP  1024          // per-class staging capacity (4 x 256 sub-regions)
#define SUBCAP 256          // per-sub-region capacity (250 boxes per residue max)
#define NB    128           // histogram buckets (score bits >>19, rebased)
#define HBASE 1952          // (0x3D000000 >> 19): bucket of p = 1/32
#define TARGET 256          // candidate prefix size (>=100 survivors w/ margin)
#define PC 0.03125f         // stage only p >= 1/32 (bucket-aligned)

typedef unsigned long long u64;
typedef unsigned int u32;

// globals zero-initialized at load; every invocation self-cleans.
__device__ int    g_bcnt4[BATCH * NCLS * 4];       // per-(class, n&3) staged counts
__device__ u64    g_bstage[BATCH * NCLS * BCAP];   // per-class staged keys (4 sub-regions)
__device__ u32    g_hist [BATCH * NB];             // candidate score histogram
__device__ u32    g_hist2[BATCH * NB];             // survivor score histogram
__device__ int    g_scnt2[BATCH];                  // survivor counts
__device__ u64    g_surv[BATCH * CAND];            // survivor keys
__device__ float4 g_cbox[BATCH * NCLS * BCAP];     // survivor boxes by (c, rank)

__device__ __forceinline__ int bkt(u32 sb) {
    int v = (int)(sb >> 19) - HBASE;
    v = v < 0 ? 0 : v;
    return v > NB - 1 ? NB - 1 : v;
}

// ---------------------------------------------------------------------------
// K1: single-pass softmax; stage (score, ~boxidx) into per-(class, n&3)
// sub-buckets (4x less atomic contention); histogram score bits.
// One warp per (b, n). 250 blocks x 256.
// ---------------------------------------------------------------------------
__global__ __launch_bounds__(256) void score_kernel(const float* __restrict__ cls) {
    int gw   = (blockIdx.x * blockDim.x + threadIdx.x) >> 5;
    int lane = threadIdx.x & 31;
    if (gw >= BATCH * NBOX) { cudaTriggerProgrammaticLaunchCompletion(); return; }
    int b = gw / NBOX, n = gw % NBOX;

    const float* lg = cls + (size_t)(b * NBOX + n) * 81;

    float v0 = lg[lane];
    float v1 = lg[lane + 32];
    bool  ok2 = (lane + 64) < 81;
    float v2 = ok2 ? lg[lane + 64] : -1e30f;

    float mx = fmaxf(fmaxf(v0, v1), v2);
    #pragma unroll
    for (int o = 16; o; o >>= 1) mx = fmaxf(mx, __shfl_xor_sync(0xffffffffu, mx, o));

    float e0 = expf(v0 - mx);
    float e1 = expf(v1 - mx);
    float e2 = ok2 ? expf(v2 - mx) : 0.f;

    float s = e0 + e1 + e2;
    #pragma unroll
    for (int o = 16; o; o >>= 1) s += __shfl_xor_sync(0xffffffffu, s, o);
    float inv = 1.f / s;

    float pr[3] = { e0 * inv, e1 * inv, e2 * inv };
    int r = n & 3;                               // staging sub-region

    #pragma unroll
    for (int h = 0; h < 3; h++) {
        int idx = lane + 32 * h;                 // logit index 0..80
        float p = pr[h];
        if (idx >= 1 && idx <= 80 && p >= PC) {
            u32 sb = __float_as_uint(p);
            int ci = b * NCLS + (idx - 1);
            atomicAdd(&g_hist[b * NB + bkt(sb)], 1u);
            int pos = atomicAdd(&g_bcnt4[ci * 4 + r], 1);   // < 250 always
            g_bstage[(size_t)ci * BCAP + r * SUBCAP + pos] =
                ((u64)sb << 10) | (u32)(1023 - n);
        }
    }
    cudaTriggerProgrammaticLaunchCompletion();
}

// ---------------------------------------------------------------------------
// warp 0 helper: suffix-scan a 128-bucket histogram (4 buckets/lane).
//   mode 0: max(max v: suf>=TARGET, min v: suf<=CAND)  (candidates)
//   mode 1: max v: suf >= NCAND                        (survivors)
// ---------------------------------------------------------------------------
__device__ __forceinline__ int warp_threshold(const u32* hist, int mode) {
    int lane = threadIdx.x & 31;
    u32 h[4]; u32 L = 0;
    #pragma unroll
    for (int q = 0; q < 4; q++) { h[q] = hist[lane * 4 + q]; L += h[q]; }

    u32 x = L;                                    // inclusive suffix over lanes
    #pragma unroll
    for (int off = 1; off < 32; off <<= 1) {
        u32 t = __shfl_down_sync(0xffffffffu, x, off);
        if (lane + off < 32) x += t;
    }
    u32 run = x - L;                              // suffix strictly after chunk
    int t1 = 0, t2 = NB - 1;
    #pragma unroll
    for (int q = 3; q >= 0; q--) {
        u32 suf = run + h[q];
        int v = lane * 4 + q;
        if (mode == 0) {
            if (suf >= TARGET && v > t1) t1 = v;
            if (suf <= CAND   && v < t2) t2 = v;
        } else {
            if (suf >= NCAND  && v > t1) t1 = v;
        }
        run = suf;
    }
    #pragma unroll
    for (int off = 16; off; off >>= 1) {
        int a  = __shfl_xor_sync(0xffffffffu, t1, off);
        int bb = __shfl_xor_sync(0xffffffffu, t2, off);
        t1 = a  > t1 ? a  : t1;
        t2 = bb < t2 ? bb : t2;
    }
    return (mode == 0) ? (t1 > t2 ? t1 : t2) : t1;
}

// ---------------------------------------------------------------------------
// K2: per (b, class) — PDL wait, in-block threshold, filter (4 sub-regions),
// sort, decode, NMS, emit survivors. grid = BATCH*NCLS, block = 128.
// ---------------------------------------------------------------------------
__global__ __launch_bounds__(128) void class_nms_kernel(
        const float* __restrict__ box,
        const float* __restrict__ anc,
        const float* __restrict__ info) {
    __shared__ u64 skey[BCAP];
    __shared__ float4 sbx[BCAP];
    __shared__ unsigned char sflag[BCAP];
    __shared__ int s_n, s_cnt, s_base, s_tb;

    // wait until score_kernel is complete and its writes are visible
    cudaGridDependencySynchronize();

    int tid = threadIdx.x;
    int ci  = blockIdx.x;
    int b   = ci / NCLS;
    int c   = ci % NCLS;

    // hoist the 4 sub-region counts (independent of the threshold scan)
    int m0 = g_bcnt4[ci * 4 + 0];
    int m1 = g_bcnt4[ci * 4 + 1];
    int m2 = g_bcnt4[ci * 4 + 2];
    int m3 = g_bcnt4[ci * 4 + 3];

    if (tid == 0) s_n = 0;
    // warp 0: candidate threshold bucket (redundant per block; deterministic)
    if (tid < 32) {
        int tb = warp_threshold(g_hist + b * NB, 0);
        if (tid == 0) s_tb = tb;
    }
    __syncthreads();

    // filter staged keys (4 sub-regions) by threshold bucket
    int tb = s_tb;
    int mr[4] = { m0, m1, m2, m3 };
    #pragma unroll
    for (int r = 0; r < 4; r++) {
        for (int i = tid; i < mr[r]; i += 128) {
            u64 k = g_bstage[(size_t)ci * BCAP + r * SUBCAP + i];
            if (bkt((u32)(k >> 10)) >= tb) {
                int p = atomicAdd(&s_n, 1);
                skey[p] = k;
            }
        }
    }
    __syncthreads();
    int n = s_n;
    if (tid < 4) g_bcnt4[ci * 4 + tid] = 0;   // cleanup for next invocation
    if (n == 0) { cudaTriggerProgrammaticLaunchCompletion(); return; }

    // pad to pow2, bitonic sort descending (score, ~boxidx)
    int P = 32; while (P < n) P <<= 1;
    for (int e = tid; e < P; e += 128) if (e >= n) skey[e] = 0ull;
    for (unsigned k = 2; k <= (unsigned)P; k <<= 1) {
        for (unsigned j = k >> 1; j > 0; j >>= 1) {
            __syncthreads();
            for (int e = tid; e < P; e += 128) {
                int ixj = e ^ (int)j;
                if (ixj > e) {
                    u64 va = skey[e], vb = skey[ixj];
                    bool desc = ((e & (int)k) == 0);
                    if (desc ? (va < vb) : (va > vb)) { skey[e] = vb; skey[ixj] = va; }
                }
            }
        }
    }
    __syncthreads();

    // decode boxes (rank order)
    float hmax = info[b * 5 + 0] - 1.f;
    float wmax = info[b * 5 + 1] - 1.f;
    for (int i = tid; i < n; i += 128) {
        u64 k = skey[i];
        int nb = 1023 - (int)(k & 0x3FFull);
        float4 a = *(const float4*)(anc + (size_t)(b * NBOX + nb) * 4);
        float ha  = a.z - a.x + 1.f;
        float wa  = a.w - a.y + 1.f;
        float cya = a.x + 0.5f * ha;
        float cxa = a.y + 0.5f * wa;
        float4 e = *(const float4*)(box + ((size_t)(b * NBOX + nb) * 81 + (c + 1)) * 4);
        float cy = (e.x / 10.f) * ha + cya;
        float cx = (e.y / 10.f) * wa + cxa;
        float h  = expf(e.z / 5.f) * ha;
        float wd = expf(e.w / 5.f) * wa;
        float ymin = fminf(fmaxf(cy - 0.5f * h,        0.f), hmax);
        float ymax = fminf(fmaxf(cy + 0.5f * h - 1.f,  0.f), hmax);
        float xmin = fminf(fmaxf(cx - 0.5f * wd,       0.f), wmax);
        float xmax = fminf(fmaxf(cx + 0.5f * wd - 1.f, 0.f), wmax);
        sbx[i]   = make_float4(ymin, xmin, ymax, xmax);
        sflag[i] = 0;
    }
    __syncthreads();

    // greedy NMS: warp 0, serial over i, j-parallel over lanes
    if (tid < 32) {
        for (int i = 0; i < n - 1; i++) {
            if (sflag[i] == 0) {
                float4 B = sbx[i];
                float ai = (B.z - B.x) * (B.w - B.y);
                for (int j = i + 1 + tid; j < n; j += 32) {
                    float4 C = sbx[j];
                    float iy = fmaxf(0.f, fminf(B.z, C.z) - fmaxf(B.x, C.x));
                    float ix = fmaxf(0.f, fminf(B.w, C.w) - fmaxf(B.y, C.y));
                    float inter = iy * ix;
                    float aj  = (C.z - C.x) * (C.w - C.y);
                    float iou = inter / fmaxf(ai + aj - inter, 1e-8f);  // exact ref
                    if (iou > 0.5f) sflag[j] = 1;
                }
            }
            __syncwarp();
        }
    }
    __syncthreads();

    // reserve global survivor slots
    if (tid == 0) s_cnt = 0;
    __syncthreads();
    int my = 0;
    for (int e = tid; e < n; e += 128) if (!sflag[e]) my++;
    if (my) atomicAdd(&s_cnt, my);
    __syncthreads();
    if (tid == 0) s_base = atomicAdd(&g_scnt2[b], s_cnt);
    __syncthreads();
    if (tid == 0) s_cnt = 0;
    __syncthreads();

    // emit survivors: key (score desc, (c,rank) asc proxy), box, histogram
    for (int e = tid; e < n; e += 128) {
        if (!sflag[e]) {
            u32 sb   = (u32)(skey[e] >> 10);
            u32 flat = (u32)(c * BCAP + e);            // rank == true class rank
            int slot = atomicAdd(&s_cnt, 1);
            g_surv[b * CAND + s_base + slot] =
                ((u64)sb << 18) | (u64)(0x3FFFFu ^ flat);
            g_cbox[(size_t)ci * BCAP + e] = sbx[e];
            atomicAdd(&g_hist2[b * NB + bkt(sb)], 1u);
        }
    }
    cudaTriggerProgrammaticLaunchCompletion();
}

// ---------------------------------------------------------------------------
// K3: per batch — PDL wait, survivor threshold for top-100, small sort,
// emit output, all cleanup. grid = BATCH, block = 128.
// ---------------------------------------------------------------------------
__global__ __launch_bounds__(128) void final_kernel(float* __restrict__ out) {
    __shared__ u64 skey[CAND];
    __shared__ int s_tb, s_n;

    // wait until class_nms_kernel is complete and its writes are visible
    cudaGridDependencySynchronize();

    int tid = threadIdx.x;
    int b   = blockIdx.x;

    int tot = g_scnt2[b];                     // hoisted (independent of scan)

    if (tid == 0) s_n = 0;
    if (tid < 32) {
        int tb = warp_threshold(g_hist2 + b * NB, 1);
        if (tid == 0) s_tb = tb;
    }
    __syncthreads();

    int tb2 = s_tb;

    // filter survivors above the bucket threshold
    for (int i = tid; i < tot; i += 128) {
        u64 k = g_surv[b * CAND + i];
        if (bkt((u32)(k >> 18)) >= tb2) {
            int p = atomicAdd(&s_n, 1);
            skey[p] = k;                      // <= CAND by construction
        }
    }
    __syncthreads();
    int n = s_n;                              // typ. ~100-150

    // cleanup early (stores overlap the sort below)
    if (tid < NB) {
        g_hist [b * NB + tid] = 0;
        g_hist2[b * NB + tid] = 0;
    }
    if (tid == 0) g_scnt2[b] = 0;

    int P = 128; while (P < n) P <<= 1;       // <= CAND
    for (int e = tid; e < P; e += 128) if (e >= n) skey[e] = 0ull;
    for (unsigned k = 2; k <= (unsigned)P; k <<= 1) {
        for (unsigned j = k >> 1; j > 0; j >>= 1) {
            __syncthreads();
            for (int e = tid; e < P; e += 128) {
                int ixj = e ^ (int)j;
                if (ixj > e) {
                    u64 va = skey[e], vb = skey[ixj];
                    bool desc = ((e & (int)k) == 0);
                    if (desc ? (va < vb) : (va > vb)) { skey[e] = vb; skey[ixj] = va; }
                }
            }
        }
    }
    __syncthreads();

    // emit top-100
    if (tid < NCAND) {
        u64 kv   = skey[tid];
        u32 sb   = (u32)(kv >> 18);
        u32 flat = 0x3FFFFu ^ ((u32)kv & 0x3FFFFu);
        int c    = (int)(flat >> 10);
        int rank = (int)(flat & (BCAP - 1));
        float4 bx = g_cbox[(size_t)(b * NCLS + c) * BCAP + rank];
        float* o = out + (size_t)(b * NCAND + tid) * 6;
        o[0] = bx.x; o[1] = bx.y; o[2] = bx.z; o[3] = bx.w;
        o[4] = __uint_as_float(sb);
        o[5] = (float)(c + 1);
    }
}

// ---------------------------------------------------------------------------
extern "C" void kernel_launch(void* const* d_in, const int* in_sizes, int n_in,
                              void* d_out, int out_size) {
    const float* cls  = (const float*)d_in[0];
    const float* box  = (const float*)d_in[1];
    const float* anc  = (const float*)d_in[2];
    const float* info = (const float*)d_in[3];

    // K1: plain launch on the capture stream
    score_kernel<<<(BATCH * NBOX * 32 + 255) / 256, 256>>>(cls);

    // K2, K3: programmatic dependent launches (overlap launch with upstream tail)
    cudaLaunchAttribute attr[1];
    attr[0].id = cudaLaunchAttributeProgrammaticStreamSerialization;
    attr[0].val.programmaticStreamSerializationAllowed = 1;

    {
        cudaLaunchConfig_t cfg = {};
        cfg.gridDim  = dim3(BATCH * NCLS, 1, 1);
        cfg.blockDim = dim3(128, 1, 1);
        cfg.dynamicSmemBytes = 0;
        cfg.stream = 0;
        cfg.attrs = attr;
        cfg.numAttrs = 1;
        cudaLaunchKernelEx(&cfg, class_nms_kernel, box, anc, info);
    }
    {
        cudaLaunchConfig_t cfg = {};
        cfg.gridDim  = dim3(BATCH, 1, 1);
        cfg.blockDim = dim3(128, 1, 1);
        cfg.dynamicSmemBytes = 0;
        cfg.stream = 0;
        cfg.attrs = attr;
        cfg.numAttrs = 1;
        cudaLaunchKernelEx(&cfg, final_kernel, (float*)d_out);
    }
}

// round 17
// speedup vs baseline: 1.3512x; 1.0715x over previous
#include <cuda_runtime.h>

#define BATCH 2
#define NBOX  1000
#define NCLS  80
#define NCAND 100
#define CAND  2048          // hard smem cap for filtered candidates per batch
#define BCAP  1024          // per-class staging capacity (4 x 256 sub-regions)
#define SUBCAP 256          // per-sub-region capacity (250 boxes per residue max)
#define NB    128           // histogram buckets (score bits >>19, rebased)
#define HBASE 1952          // (0x3D000000 >> 19): bucket of p = 1/32
#define TARGET 256          // candidate prefix size (>=100 survivors w/ margin)
#define PC 0.03125f         // stage only p >= 1/32 (bucket-aligned)

typedef unsigned long long u64;
typedef unsigned int u32;

// globals zero-initialized at load; every invocation self-cleans.
__device__ int    g_bcnt4[BATCH * NCLS * 4];       // per-(class, n&3) staged counts
__device__ u64    g_bstage[BATCH * NCLS * BCAP];   // per-class staged keys (4 sub-regions)
__device__ u32    g_hist [BATCH * NB];             // candidate score histogram
__device__ u32    g_hist2[BATCH * NB];             // survivor score histogram
__device__ int    g_scnt2[BATCH];                  // survivor counts
__device__ u64    g_surv[BATCH * CAND];            // survivor keys
__device__ float4 g_cbox[BATCH * NCLS * BCAP];     // survivor boxes by (c, rank)

__device__ __forceinline__ int bkt(u32 sb) {
    int v = (int)(sb >> 19) - HBASE;
    v = v < 0 ? 0 : v;
    return v > NB - 1 ? NB - 1 : v;
}

// ---------------------------------------------------------------------------
// K1: single-pass softmax; stage (score, ~boxidx) into per-(class, n&3)
// sub-buckets; histogram score bits. One warp per (b, n). 250 blocks x 256.
// ---------------------------------------------------------------------------
__global__ __launch_bounds__(256) void score_kernel(const float* __restrict__ cls) {
    int gw   = (blockIdx.x * blockDim.x + threadIdx.x) >> 5;
    int lane = threadIdx.x & 31;
    if (gw >= BATCH * NBOX) { cudaTriggerProgrammaticLaunchCompletion(); return; }
    int b = gw / NBOX, n = gw % NBOX;

    const float* lg = cls + (size_t)(b * NBOX + n) * 81;

    float v0 = lg[lane];
    float v1 = lg[lane + 32];
    bool  ok2 = (lane + 64) < 81;
    float v2 = ok2 ? lg[lane + 64] : -1e30f;

    float mx = fmaxf(fmaxf(v0, v1), v2);
    #pragma unroll
    for (int o = 16; o; o >>= 1) mx = fmaxf(mx, __shfl_xor_sync(0xffffffffu, mx, o));

    float e0 = expf(v0 - mx);
    float e1 = expf(v1 - mx);
    float e2 = ok2 ? expf(v2 - mx) : 0.f;

    float s = e0 + e1 + e2;
    #pragma unroll
    for (int o = 16; o; o >>= 1) s += __shfl_xor_sync(0xffffffffu, s, o);
    float inv = 1.f / s;

    float pr[3] = { e0 * inv, e1 * inv, e2 * inv };
    int r = n & 3;                               // staging sub-region

    #pragma unroll
    for (int h = 0; h < 3; h++) {
        int idx = lane + 32 * h;                 // logit index 0..80
        float p = pr[h];
        if (idx >= 1 && idx <= 80 && p >= PC) {
            u32 sb = __float_as_uint(p);
            int ci = b * NCLS + (idx - 1);
            atomicAdd(&g_hist[b * NB + bkt(sb)], 1u);
            int pos = atomicAdd(&g_bcnt4[ci * 4 + r], 1);   // < 250 always
            g_bstage[(size_t)ci * BCAP + r * SUBCAP + pos] =
                ((u64)sb << 10) | (u32)(1023 - n);
        }
    }
    cudaTriggerProgrammaticLaunchCompletion();
}

// ---------------------------------------------------------------------------
// warp 0 helper: suffix-scan a 128-bucket histogram (4 buckets/lane).
//   mode 0: max(max v: suf>=TARGET, min v: suf<=CAND)  (candidates)
//   mode 1: max v: suf >= NCAND                        (survivors)
// ---------------------------------------------------------------------------
__device__ __forceinline__ int warp_threshold(const u32* hist, int mode) {
    int lane = threadIdx.x & 31;
    u32 h[4]; u32 L = 0;
    #pragma unroll
    for (int q = 0; q < 4; q++) { h[q] = hist[lane * 4 + q]; L += h[q]; }

    u32 x = L;                                    // inclusive suffix over lanes
    #pragma unroll
    for (int off = 1; off < 32; off <<= 1) {
        u32 t = __shfl_down_sync(0xffffffffu, x, off);
        if (lane + off < 32) x += t;
    }
    u32 run = x - L;                              // suffix strictly after chunk
    int t1 = 0, t2 = NB - 1;
    #pragma unroll
    for (int q = 3; q >= 0; q--) {
        u32 suf = run + h[q];
        int v = lane * 4 + q;
        if (mode == 0) {
            if (suf >= TARGET && v > t1) t1 = v;
            if (suf <= CAND   && v < t2) t2 = v;
        } else {
            if (suf >= NCAND  && v > t1) t1 = v;
        }
        run = suf;
    }
    #pragma unroll
    for (int off = 16; off; off >>= 1) {
        int a  = __shfl_xor_sync(0xffffffffu, t1, off);
        int bb = __shfl_xor_sync(0xffffffffu, t2, off);
        t1 = a  > t1 ? a  : t1;
        t2 = bb < t2 ? bb : t2;
    }
    return (mode == 0) ? (t1 > t2 ? t1 : t2) : t1;
}

// ---------------------------------------------------------------------------
// K2: per (b, class) — PDL wait, threshold (warp 0) OVERLAPPED with raw-key
// prefetch (warps 1-3), filter from smem, sort, decode, NMS, emit survivors.
// grid = BATCH*NCLS, block = 128.
// ---------------------------------------------------------------------------
__global__ __launch_bounds__(128) void class_nms_kernel(
        const float* __restrict__ box,
        const float* __restrict__ anc,
        const float* __restrict__ info) {
    __shared__ u64 raw[BCAP];
    __shared__ u64 skey[BCAP];
    __shared__ float4 sbx[BCAP];
    __shared__ unsigned char sflag[BCAP];
    __shared__ int s_n, s_cnt, s_base, s_tb;

    // wait until score_kernel is complete and its writes are visible
    cudaGridDependencySynchronize();

    int tid = threadIdx.x;
    int ci  = blockIdx.x;
    int b   = ci / NCLS;
    int c   = ci % NCLS;

    // sub-region counts (independent loads, all threads)
    int m0 = g_bcnt4[ci * 4 + 0];
    int m1 = g_bcnt4[ci * 4 + 1];
    int m2 = g_bcnt4[ci * 4 + 2];
    int m3 = g_bcnt4[ci * 4 + 3];

    if (tid == 0) s_n = 0;

    // OVERLAP: warp 0 computes threshold; warps 1-3 prefetch raw staged keys
    if (tid < 32) {
        int tb = warp_threshold(g_hist + b * NB, 0);
        if (tid == 0) s_tb = tb;
    } else {
        int t = tid - 32;                               // 0..95
        for (int i = t; i < m0; i += 96)
            raw[i] = g_bstage[(size_t)ci * BCAP + 0 * SUBCAP + i];
        for (int i = t; i < m1; i += 96)
            raw[m0 + i] = g_bstage[(size_t)ci * BCAP + 1 * SUBCAP + i];
        for (int i = t; i < m2; i += 96)
            raw[m0 + m1 + i] = g_bstage[(size_t)ci * BCAP + 2 * SUBCAP + i];
        for (int i = t; i < m3; i += 96)
            raw[m0 + m1 + m2 + i] = g_bstage[(size_t)ci * BCAP + 3 * SUBCAP + i];
    }
    __syncthreads();

    // filter from smem by threshold bucket
    int tb = s_tb;
    int m = m0 + m1 + m2 + m3;
    for (int i = tid; i < m; i += 128) {
        u64 k = raw[i];
        if (bkt((u32)(k >> 10)) >= tb) {
            int p = atomicAdd(&s_n, 1);
            skey[p] = k;
        }
    }
    __syncthreads();
    int n = s_n;
    if (tid < 4) g_bcnt4[ci * 4 + tid] = 0;   // cleanup for next invocation
    if (n == 0) { cudaTriggerProgrammaticLaunchCompletion(); return; }

    // pad to pow2, bitonic sort descending (score, ~boxidx)
    int P = 32; while (P < n) P <<= 1;
    for (int e = tid; e < P; e += 128) if (e >= n) skey[e] = 0ull;
    for (unsigned k = 2; k <= (unsigned)P; k <<= 1) {
        for (unsigned j = k >> 1; j > 0; j >>= 1) {
            __syncthreads();
            for (int e = tid; e < P; e += 128) {
                int ixj = e ^ (int)j;
                if (ixj > e) {
                    u64 va = skey[e], vb = skey[ixj];
                    bool desc = ((e & (int)k) == 0);
                    if (desc ? (va < vb) : (va > vb)) { skey[e] = vb; skey[ixj] = va; }
                }
            }
        }
    }
    __syncthreads();

    // decode boxes (rank order)
    float hmax = info[b * 5 + 0] - 1.f;
    float wmax = info[b * 5 + 1] - 1.f;
    for (int i = tid; i < n; i += 128) {
        u64 k = skey[i];
        int nb = 1023 - (int)(k & 0x3FFull);
        float4 a = *(const float4*)(anc + (size_t)(b * NBOX + nb) * 4);
        float ha  = a.z - a.x + 1.f;
        float wa  = a.w - a.y + 1.f;
        float cya = a.x + 0.5f * ha;
        float cxa = a.y + 0.5f * wa;
        float4 e = *(const float4*)(box + ((size_t)(b * NBOX + nb) * 81 + (c + 1)) * 4);
        float cy = (e.x / 10.f) * ha + cya;
        float cx = (e.y / 10.f) * wa + cxa;
        float h  = expf(e.z / 5.f) * ha;
        float wd = expf(e.w / 5.f) * wa;
        float ymin = fminf(fmaxf(cy - 0.5f * h,        0.f), hmax);
        float ymax = fminf(fmaxf(cy + 0.5f * h - 1.f,  0.f), hmax);
        float xmin = fminf(fmaxf(cx - 0.5f * wd,       0.f), wmax);
        float xmax = fminf(fmaxf(cx + 0.5f * wd - 1.f, 0.f), wmax);
        sbx[i]   = make_float4(ymin, xmin, ymax, xmax);
        sflag[i] = 0;
    }
    __syncthreads();

    // greedy NMS: warp 0, serial over i, j-parallel over lanes
    if (tid < 32) {
        for (int i = 0; i < n - 1; i++) {
            if (sflag[i] == 0) {
                float4 B = sbx[i];
                float ai = (B.z - B.x) * (B.w - B.y);
                for (int j = i + 1 + tid; j < n; j += 32) {
                    float4 C = sbx[j];
                    float iy = fmaxf(0.f, fminf(B.z, C.z) - fmaxf(B.x, C.x));
                    float ix = fmaxf(0.f, fminf(B.w, C.w) - fmaxf(B.y, C.y));
                    float inter = iy * ix;
                    float aj  = (C.z - C.x) * (C.w - C.y);
                    float iou = inter / fmaxf(ai + aj - inter, 1e-8f);  // exact ref
                    if (iou > 0.5f) sflag[j] = 1;
                }
            }
            __syncwarp();
        }
    }
    __syncthreads();

    // reserve global survivor slots
    if (tid == 0) s_cnt = 0;
    __syncthreads();
    int my = 0;
    for (int e = tid; e < n; e += 128) if (!sflag[e]) my++;
    if (my) atomicAdd(&s_cnt, my);
    __syncthreads();
    if (tid == 0) s_base = atomicAdd(&g_scnt2[b], s_cnt);
    __syncthreads();
    if (tid == 0) s_cnt = 0;
    __syncthreads();

    // emit survivors: key (score desc, (c,rank) asc proxy), box, histogram
    for (int e = tid; e < n; e += 128) {
        if (!sflag[e]) {
            u32 sb   = (u32)(skey[e] >> 10);
            u32 flat = (u32)(c * BCAP + e);            // rank == true class rank
            int slot = atomicAdd(&s_cnt, 1);
            g_surv[b * CAND + s_base + slot] =
                ((u64)sb << 18) | (u64)(0x3FFFFu ^ flat);
            g_cbox[(size_t)ci * BCAP + e] = sbx[e];
            atomicAdd(&g_hist2[b * NB + bkt(sb)], 1u);
        }
    }
    cudaTriggerProgrammaticLaunchCompletion();
}

// ---------------------------------------------------------------------------
// K3: per batch — PDL wait, threshold (warp 0) OVERLAPPED with survivor
// prefetch (warps 1-3), filter, small sort, emit output, all cleanup.
// grid = BATCH, block = 128.
// ---------------------------------------------------------------------------
__global__ __launch_bounds__(128) void final_kernel(float* __restrict__ out) {
    __shared__ u64 sraw[CAND];
    __shared__ u64 skey[CAND];
    __shared__ int s_tb, s_n;

    // wait until class_nms_kernel is complete and its writes are visible
    cudaGridDependencySynchronize();

    int tid = threadIdx.x;
    int b   = blockIdx.x;

    int tot = g_scnt2[b];                     // hoisted (independent load)

    if (tid == 0) s_n = 0;

    // OVERLAP: warp 0 computes threshold; warps 1-3 prefetch survivor keys
    if (tid < 32) {
        int tb = warp_threshold(g_hist2 + b * NB, 1);
        if (tid == 0) s_tb = tb;
    } else {
        int t = tid - 32;                     // 0..95
        for (int i = t; i < tot; i += 96)
            sraw[i] = g_surv[b * CAND + i];
    }
    __syncthreads();

    int tb2 = s_tb;

    // filter survivors above the bucket threshold (from smem)
    for (int i = tid; i < tot; i += 128) {
        u64 k = sraw[i];
        if (bkt((u32)(k >> 18)) >= tb2) {
            int p = atomicAdd(&s_n, 1);
            skey[p] = k;                      // <= CAND by construction
        }
    }
    __syncthreads();
    int n = s_n;                              // typ. ~100-150

    // cleanup early (stores overlap the sort below)
    if (tid < NB) {
        g_hist [b * NB + tid] = 0;
        g_hist2[b * NB + tid] = 0;
    }
    if (tid == 0) g_scnt2[b] = 0;

    int P = 128; while (P < n) P <<= 1;       // <= CAND
    for (int e = tid; e < P; e += 128) if (e >= n) skey[e] = 0ull;
    for (unsigned k = 2; k <= (unsigned)P; k <<= 1) {
        for (unsigned j = k >> 1; j > 0; j >>= 1) {
            __syncthreads();
            for (int e = tid; e < P; e += 128) {
                int ixj = e ^ (int)j;
                if (ixj > e) {
                    u64 va = skey[e], vb = skey[ixj];
                    bool desc = ((e & (int)k) == 0);
                    if (desc ? (va < vb) : (va > vb)) { skey[e] = vb; skey[ixj] = va; }
                }
            }
        }
    }
    __syncthreads();

    // emit top-100
    if (tid < NCAND) {
        u64 kv   = skey[tid];
        u32 sb   = (u32)(kv >> 18);
        u32 flat = 0x3FFFFu ^ ((u32)kv & 0x3FFFFu);
        int c    = (int)(flat >> 10);
        int rank = (int)(flat & (BCAP - 1));
        float4 bx = g_cbox[(size_t)(b * NCLS + c) * BCAP + rank];
        float* o = out + (size_t)(b * NCAND + tid) * 6;
        o[0] = bx.x; o[1] = bx.y; o[2] = bx.z; o[3] = bx.w;
        o[4] = __uint_as_float(sb);
        o[5] = (float)(c + 1);
    }
}

// ---------------------------------------------------------------------------
extern "C" void kernel_launch(void* const* d_in, const int* in_sizes, int n_in,
                              void* d_out, int out_size) {
    const float* cls  = (const float*)d_in[0];
    const float* box  = (const float*)d_in[1];
    const float* anc  = (const float*)d_in[2];
    const float* info = (const float*)d_in[3];

    // K1: plain launch on the capture stream
    score_kernel<<<(BATCH * NBOX * 32 + 255) / 256, 256>>>(cls);

    // K2, K3: programmatic dependent launches (overlap launch with upstream tail)
    cudaLaunchAttribute attr[1];
    attr[0].id = cudaLaunchAttributeProgrammaticStreamSerialization;
    attr[0].val.programmaticStreamSerializationAllowed = 1;

    {
        cudaLaunchConfig_t cfg = {};
        cfg.gridDim  = dim3(BATCH * NCLS, 1, 1);
        cfg.blockDim = dim3(128, 1, 1);
        cfg.dynamicSmemBytes = 0;
        cfg.stream = 0;
        cfg.attrs = attr;
        cfg.numAttrs = 1;
        cudaLaunchKernelEx(&cfg, class_nms_kernel, box, anc, info);
    }
    {
        cudaLaunchConfig_t cfg = {};
        cfg.gridDim  = dim3(BATCH, 1, 1);
        cfg.blockDim = dim3(128, 1, 1);
        cfg.dynamicSmemBytes = 0;
        cfg.stream = 0;
        cfg.attrs = attr;
        cfg.numAttrs = 1;
        cudaLaunchKernelEx(&cfg, final_kernel, (float*)d_out);
    }
}